// round 17
// baseline (speedup 1.0000x reference)
#include <cuda_runtime.h>
#include <cuda_bf16.h>
#include <cstdint>

#define T_LEN      131072
#define T_PAD      131076                // divisible by 36
#define N_ST       256
#define ROWS_CHUNK 36
#define CBUF_BYTES (ROWS_CHUNK * 1024)   // 36KB
#define NCHUNK     (T_PAD / ROWS_CHUNK)  // 3641
#define UHALF      6144                  // 12 u slots x 512B per chunk half
#define SMEM_TOTAL (3 * CBUF_BYTES + 2 * UHALF + 128)
#define FLT_MIN_N  1.17549435e-38f

typedef unsigned long long ull;

// cost rows t (t>=T_LEN stay zero: device globals zero-init)
static __device__ float g_cost[(size_t)(T_PAD + 64) * N_ST];
// exported u rows: row g = u_{3g+2}, g = 0..NCHUNK*12-1
static __device__ float g_u3[(size_t)(NCHUNK * 12) * 128];

// ---- packed f32x2 primitives (each half RN-rounds independently == FADD) ----
__device__ __forceinline__ ull add2p(ull a, ull b) {
    ull r;
    asm("add.rn.f32x2 %0, %1, %2;" : "=l"(r) : "l"(a), "l"(b));
    return r;
}
__device__ __forceinline__ float hminp(ull x) {   // min of the two packed halves
    float lo, hi;
    asm("mov.b64 {%0, %1}, %2;" : "=f"(lo), "=f"(hi) : "l"(x));  // reg naming only
    return fminf(lo, hi);
}
__device__ __forceinline__ ull packf(float lo, float hi) {
    ull r;
    asm("mov.b64 %0, {%1, %2};" : "=l"(r) : "f"(lo), "f"(hi));   // reg naming only
    return r;
}
__device__ __forceinline__ void ld2u64(unsigned a, ull& x, ull& y) {
    asm volatile("ld.shared.v2.u64 {%0, %1}, [%2];"
                 : "=l"(x), "=l"(y) : "r"(a) : "memory");
}

// ---------------------------------------------------------------------------
// Phase A: parallel likelihoods (R6-validated FTZ emulation). Rows t%3==1
// stored permuted for trellis step B:
//   pos(j) = 128*(j>>7) + 4*((j&63)>>1) + 2*((j>>6)&1) + (j&1)
// ---------------------------------------------------------------------------
__global__ void __launch_bounds__(256) va_cost_kernel(const float* __restrict__ rx,
                                                      const float* __restrict__ h,
                                                      float* __restrict__ out) {
    __shared__ float sp[N_ST];
    __shared__ float hs[8];
    const int tid = threadIdx.x;
    if (tid < 8) hs[tid] = h[tid];
    __syncthreads();
    {
        float acc = 0.0f;
#pragma unroll
        for (int j = 0; j < 8; ++j) {
            float sym = ((tid >> (7 - j)) & 1) ? -1.0f : 1.0f;
            acc += sym * hs[j];
        }
        sp[tid] = acc;
    }
    __syncthreads();

    const int lane = tid & 31;
    const int t    = blockIdx.x * 8 + (tid >> 5);
    const float r  = rx[t];
    const bool permB = (t % 3) == 1;

    float p[8];
    float acc = 0.0f;
#pragma unroll
    for (int k = 0; k < 8; ++k) {
        float d = r - sp[lane + 32 * k];
        float a = (-(d * d)) / 0.2f;
        float e = expf(a);
        p[k] = (e < FLT_MIN_N) ? 0.0f : e;   // FTZ
        acc += p[k];
    }
#pragma unroll
    for (int off = 16; off > 0; off >>= 1)
        acc += __shfl_down_sync(0xffffffffu, acc, off);
    const float S = __shfl_sync(0xffffffffu, acc, 0);

    float bv = -1.0f; int bi = 0;
#pragma unroll
    for (int k = 0; k < 8; ++k) {
        float q = __fdiv_rn(p[k], S);
        q = (q < FLT_MIN_N) ? 0.0f : q;      // FTZ
        int s = lane + 32 * k;
        if (q > bv) { bv = q; bi = s; }
        int pos = s;
        if (permB) {
            int rr = s & 63;
            pos = 128 * (s >> 7) + 4 * (rr >> 1) + 2 * ((s >> 6) & 1) + (rr & 1);
        }
        g_cost[(size_t)t * N_ST + pos] = -logf(q);
    }
#pragma unroll
    for (int off = 16; off > 0; off >>= 1) {
        float ov = __shfl_xor_sync(0xffffffffu, bv, off);
        int   oi = __shfl_xor_sync(0xffffffffu, bi, off);
        if (ov > bv || (ov == bv && oi < bi)) { bv = ov; bi = oi; }
    }

    if (lane == 0) {
        out[T_LEN + t]     = (float)(bi & 1);
        out[2 * T_LEN + t] = bv;
    }
}

// --- asm helpers ------------------------------------------------------------
__device__ __forceinline__ void st_rel(int* p, int v) {
    asm volatile("st.release.cta.shared.b32 [%0], %1;"
                 :: "r"((unsigned)__cvta_generic_to_shared(p)), "r"(v) : "memory");
}
__device__ __forceinline__ int ld_acq(int* p) {
    int v;
    asm volatile("ld.acquire.cta.shared.b32 %0, [%1];"
                 : "=r"(v) : "r"((unsigned)__cvta_generic_to_shared(p)) : "memory");
    return v;
}
__device__ __forceinline__ void mbar_init(unsigned a, unsigned cnt) {
    asm volatile("mbarrier.init.shared.b64 [%0], %1;" :: "r"(a), "r"(cnt) : "memory");
}
__device__ __forceinline__ void mbar_expect_tx(unsigned a, unsigned bytes) {
    asm volatile("mbarrier.arrive.expect_tx.shared.b64 _, [%0], %1;"
                 :: "r"(a), "r"(bytes) : "memory");
}
__device__ __forceinline__ void mbar_wait(unsigned a, int par) {
    asm volatile(
        "{\n\t.reg .pred P;\n"
        "W%=:\n\t"
        "mbarrier.try_wait.parity.acquire.cta.shared::cta.b64 P, [%0], %1, 0x989680;\n\t"
        "@!P bra W%=;\n\t}"
        :: "r"(a), "r"(par) : "memory");
}
__device__ __forceinline__ void bulk_g2s(unsigned sdst, const void* gsrc,
                                         unsigned bytes, unsigned mbar) {
    asm volatile("cp.async.bulk.shared::cta.global.mbarrier::complete_tx::bytes "
                 "[%0], [%1], %2, [%3];"
                 :: "r"(sdst), "l"(gsrc), "r"(bytes), "r"(mbar) : "memory");
}
__device__ __forceinline__ void sts_f32(unsigned a, float v) {
    asm volatile("st.shared.f32 [%0], %1;" :: "r"(a), "f"(v) : "memory");
}

// ---------------------------------------------------------------------------
// Phase B: 3-phase trellis, packed-u64 dataflow end-to-end (costs loaded as
// f32-pairs via ld.shared.v2.u64; add.rn.f32x2 on pairs; only the pair-min
// unpacks, which is register naming, not a SASS op). Converged-warp STS->LDS
// exchange (validated R16), exports only u_{3g+2}.
// ---------------------------------------------------------------------------
__global__ void __launch_bounds__(64) va_viterbi_kernel() {
    extern __shared__ char smem[];
    char* cbuf = smem;                       // 3 x 36KB cost buffers
    char* ubuf = smem + 3 * CBUF_BYTES;      // 2 x 6KB u halves (12 slots each)
    char* ctrl = ubuf + 2 * UHALF;
    int*  prod = (int*)(ctrl + 64);
    int*  done = (int*)(ctrl + 96);
    const unsigned mb0 = (unsigned)__cvta_generic_to_shared(ctrl);
    const unsigned ubase = (unsigned)__cvta_generic_to_shared(ubuf);
    const unsigned cbase = (unsigned)__cvta_generic_to_shared(cbuf);

    const int tid  = threadIdx.x;
    const int lane = tid & 31;
    const int warp = tid >> 5;

    if (tid == 0) {
        mbar_init(mb0, 1); mbar_init(mb0 + 8, 1); mbar_init(mb0 + 16, 1);
        *prod = 0; *done = -1;
    }
    __syncthreads();

    if (warp == 0) {
        if (lane == 0) {
#pragma unroll
            for (int b = 0; b < 3; ++b) {
                mbar_expect_tx(mb0 + b * 8, CBUF_BYTES);
                bulk_g2s(cbase + b * CBUF_BYTES,
                         g_cost + (size_t)b * ROWS_CHUNK * N_ST, CBUF_BYTES, mb0 + b * 8);
            }
        }

        ull Q01 = 0ull, Q23 = 0ull;               // u_0 = zeros, packed pairs
        const unsigned off16 = (unsigned)(16 * lane);
        const unsigned off4  = (unsigned)(4 * lane);
        const unsigned gath  = (unsigned)((32 * lane) & 511);
        const unsigned off32 = (unsigned)(32 * lane);

        for (int c = 0; c < NCHUNK; ++c) {
            const int b   = c % 3;
            const int par = (c / 3) & 1;
            mbar_wait(mb0 + b * 8, par);          // cost chunk resident
            while (ld_acq(done) < c - 2) { }      // our u half free

            const unsigned crow0 = cbase + (unsigned)(b * CBUF_BYTES);
            const unsigned uh    = ubase + (unsigned)((c & 1) * UHALF);
#pragma unroll
            for (int g = 0; g < 12; ++g) {
                const unsigned crow = crow0 + (unsigned)(g * 3072);
                ull CA0, CA1, CB0, CB1, DA0, DA1, DB0, DB1, EA0, EA1, EB0, EB1;
                ld2u64(crow + off16,        CA0, CA1);
                ld2u64(crow + 512 + off16,  CB0, CB1);
                ld2u64(crow + 1024 + off16, DA0, DA1);
                ld2u64(crow + 1536 + off16, DB0, DB1);
                ld2u64(crow + 2048 + off32,      EA0, EA1);
                ld2u64(crow + 2048 + off32 + 16, EB0, EB1);

                // ---- step A (local): Q -> P ----
                float p0 = hminp(add2p(Q01, CA0));   // u'[2L]
                float p1 = hminp(add2p(Q23, CA1));   // u'[2L+1]
                float p2 = hminp(add2p(Q01, CB0));   // u'[2L+64]
                float p3 = hminp(add2p(Q23, CB1));   // u'[2L+65]
                ull P01 = packf(p0, p1), P23 = packf(p2, p3);

                // ---- step B (local): P -> S, permuted costs; export u_{3g+2} ----
                float s0 = hminp(add2p(P01, DA0));   // u''[L]
                float s1 = hminp(add2p(P23, DA1));   // u''[L+32]
                float s2 = hminp(add2p(P01, DB0));   // u''[L+64]
                float s3 = hminp(add2p(P23, DB1));   // u''[L+96]
                const unsigned slB = uh + (unsigned)(g * 512);
                sts_f32(slB + off4,        s0);
                sts_f32(slB + 128 + off4,  s1);
                sts_f32(slB + 256 + off4,  s2);
                sts_f32(slB + 384 + off4,  s3);

                // ---- step C (exchange): same-warp ordered gather from slB ----
                ull G0, G1, G2, G3;
                ld2u64(slB + gath,      G0, G1);     // u''[8L'..8L'+3]
                ld2u64(slB + gath + 16, G2, G3);     // u''[8L'+4..8L'+7]
                float q0 = hminp(add2p(G0, EA0));
                float q1 = hminp(add2p(G1, EA1));
                float q2 = hminp(add2p(G2, EB0));
                float q3 = hminp(add2p(G3, EB1));
                Q01 = packf(q0, q1); Q23 = packf(q2, q3);
            }

            __syncwarp();   // cross-warp visibility for the flush (1 per 36 steps)
            if (lane == 0) {
                st_rel(prod, c + 1);
                if (c + 3 < NCHUNK) {
                    mbar_expect_tx(mb0 + b * 8, CBUF_BYTES);
                    bulk_g2s(cbase + (unsigned)(b * CBUF_BYTES),
                             g_cost + (size_t)(c + 3) * ROWS_CHUNK * N_ST,
                             CBUF_BYTES, mb0 + b * 8);
                }
            }
        }
    } else {
        // warp 1: flush 6KB halves (12 rows/chunk) to g_u3
        if (lane == 0) {
            for (int c = 0; c < NCHUNK; ++c) {
                while (ld_acq(prod) < c + 1) { }
                asm volatile("fence.proxy.async.shared::cta;" ::: "memory");
                unsigned ssrc = (unsigned)__cvta_generic_to_shared(ubuf + (c & 1) * UHALF);
                float* gdst = g_u3 + (size_t)c * 12 * 128;
                asm volatile("cp.async.bulk.global.shared::cta.bulk_group [%0], [%1], %2;"
                             :: "l"(gdst), "r"(ssrc), "r"((unsigned)UHALF) : "memory");
                asm volatile("cp.async.bulk.commit_group;" ::: "memory");
                asm volatile("cp.async.bulk.wait_group 0;" ::: "memory");
                st_rel(done, c);
            }
        }
    }
}

// ---------------------------------------------------------------------------
// Phase C: parallel bits. One warp per t; u_t obtained by:
//  t%3==2: direct read of export row (t-2)/3.
//  t%3==0 (t>=3): 1-step recompute from u_{t-1}; t==0: bit = 0.
//  t%3==1 (t>=4): 2-step recompute from u_{t-2}; t==1: from u_0 = zeros.
// All recomputes use rnd(a+b)/fminf identical to the reference recursion.
// ---------------------------------------------------------------------------
__global__ void __launch_bounds__(256) va_bits_kernel(float* __restrict__ out) {
    const int lane = threadIdx.x & 31;
    const int t    = blockIdx.x * 8 + (threadIdx.x >> 5);
    if (t == 0) { if (lane == 0) out[0] = 0.0f; return; }

    float4 uu;
    const int r = t % 3;
    if (r == 2) {
        uu = *(const float4*)(g_u3 + (size_t)((t - 2) / 3) * 128 + lane * 4);
    } else if (r == 0) {
        const float* up = g_u3 + (size_t)(t / 3 - 1) * 128;        // u_{t-1}
        const float* cp = g_cost + (size_t)(t - 1) * N_ST;
        const int ub = (8 * lane) & 127;
        float4 U0 = *(const float4*)(up + ub);
        float4 U1 = *(const float4*)(up + ub + 4);
        float4 C0 = *(const float4*)(cp + 8 * lane);
        float4 C1 = *(const float4*)(cp + 8 * lane + 4);
        uu.x = fminf(U0.x + C0.x, U0.y + C0.y);
        uu.y = fminf(U0.z + C0.z, U0.w + C0.w);
        uu.z = fminf(U1.x + C1.x, U1.y + C1.y);
        uu.w = fminf(U1.z + C1.z, U1.w + C1.w);
    } else if (t == 1) {
        const float* cp = g_cost;                                   // row 0
        float4 C0 = *(const float4*)(cp + 8 * lane);
        float4 C1 = *(const float4*)(cp + 8 * lane + 4);
        uu.x = fminf(C0.x, C0.y);    // u_0 = 0; rnd(0+c) = c exactly
        uu.y = fminf(C0.z, C0.w);
        uu.z = fminf(C1.x, C1.y);
        uu.w = fminf(C1.z, C1.w);
    } else {
        const int G = (t - 1) / 3;                                  // t = 3G+1, G>=1
        const float* up = g_u3 + (size_t)(G - 1) * 128;             // u_{t-2}
        const float* c1 = g_cost + (size_t)(t - 2) * N_ST;
        const float* c2 = g_cost + (size_t)(t - 1) * N_ST;
        const int ub  = (16 * lane) & 127;
        const int cb1 = (16 * lane) & 255;
        float4 V0 = *(const float4*)(up + ub);
        float4 V1 = *(const float4*)(up + ub + 4);
        float4 V2 = *(const float4*)(up + ub + 8);
        float4 V3 = *(const float4*)(up + ub + 12);
        float4 A0 = *(const float4*)(c1 + cb1);
        float4 A1 = *(const float4*)(c1 + cb1 + 4);
        float4 A2 = *(const float4*)(c1 + cb1 + 8);
        float4 A3 = *(const float4*)(c1 + cb1 + 12);
        float w0 = fminf(V0.x + A0.x, V0.y + A0.y);
        float w1 = fminf(V0.z + A0.z, V0.w + A0.w);
        float w2 = fminf(V1.x + A1.x, V1.y + A1.y);
        float w3 = fminf(V1.z + A1.z, V1.w + A1.w);
        float w4 = fminf(V2.x + A2.x, V2.y + A2.y);
        float w5 = fminf(V2.z + A2.z, V2.w + A2.w);
        float w6 = fminf(V3.x + A3.x, V3.y + A3.y);
        float w7 = fminf(V3.z + A3.z, V3.w + A3.w);
        float4 B0 = *(const float4*)(c2 + 8 * lane);
        float4 B1 = *(const float4*)(c2 + 8 * lane + 4);
        uu.x = fminf(w0 + B0.x, w1 + B0.y);
        uu.y = fminf(w2 + B0.z, w3 + B0.w);
        uu.z = fminf(w4 + B1.x, w5 + B1.y);
        uu.w = fminf(w6 + B1.z, w7 + B1.w);
    }

    const int base_li = 4 * lane;
    float lv = uu.x; int li = base_li;
    if (uu.y < lv) { lv = uu.y; li = base_li + 1; }
    if (uu.z < lv) { lv = uu.z; li = base_li + 2; }
    if (uu.w < lv) { lv = uu.w; li = base_li + 3; }
    unsigned lb = __float_as_uint(lv);
    unsigned mv, idx;
    asm volatile("redux.sync.min.u32 %0, %1, 0xffffffff;" : "=r"(mv) : "r"(lb));
    unsigned cand = (lb == mv) ? (unsigned)li : 0xffffffffu;
    asm volatile("redux.sync.min.u32 %0, %1, 0xffffffff;" : "=r"(idx) : "r"(cand));
    if (lane == 0) out[t] = (idx & 1u) ? 1.0f : 0.0f;
}

// ---------------------------------------------------------------------------
// out layout = [detected(T) | confident_bits(T) | confidence(T)], f32.
// ---------------------------------------------------------------------------
extern "C" void kernel_launch(void* const* d_in, const int* in_sizes, int n_in,
                              void* d_out, int out_size) {
    const float* rx = (const float*)d_in[0];
    const float* h  = (const float*)d_in[1];
    if (n_in >= 2 && in_sizes[0] == 8) {   // defensive: inputs swapped
        rx = (const float*)d_in[1];
        h  = (const float*)d_in[0];
    }
    float* out = (float*)d_out;
    cudaFuncSetAttribute(va_viterbi_kernel,
                         cudaFuncAttributeMaxDynamicSharedMemorySize, SMEM_TOTAL);
    va_cost_kernel<<<T_LEN / 8, 256>>>(rx, h, out);
    va_viterbi_kernel<<<1, 64, SMEM_TOTAL>>>();
    va_bits_kernel<<<T_LEN / 8, 256>>>(out);
}